// round 10
// baseline (speedup 1.0000x reference)
#include <cuda_runtime.h>
#include <math.h>

#define NB   4
#define LEN  64
#define DM   128
#define DI   256
#define DS   16
#define DTR  8
#define EPSF 1e-5f
#define NBLK 64
#define NTHR 256

// ------------------------- device scratch (no allocs) -------------------------
__device__ __align__(16) float g_res[NB*LEN*DM];   // residual      [b][t][j]
__device__ __align__(16) float g_hn [NB*LEN*DM];   // rmsnormed     [b][t][j]
__device__ __align__(16) float g_ucm[NB*DI*LEN];   // u=silu(conv)  [b][c][t]
__device__ __align__(16) float g_zs [NB*DI*LEN];   // silu(z)       [b][c][t]
__device__ __align__(16) float g_dt [NB*DI*LEN];   // softplus dt   [b][c][t]
__device__ __align__(16) float g_ys [NB*LEN*DI];   // y*silu(z)     [b][t][c]
__device__ __align__(16) float g_Bm [NB*LEN*DS];   // [b][t][n]
__device__ __align__(16) float g_Cm [NB*LEN*DS];   // [b][t][n]

__device__ unsigned g_barcnt = 0;   // monotonic arrivals
__device__ unsigned g_relgen = 0;   // monotonic release generation

__device__ __forceinline__ float siluf(float x){ return x / (1.0f + __expf(-x)); }
__device__ __forceinline__ float geluf(float x){ return 0.5f*x*(1.0f + erff(x*0.70710678118654752f)); }
__device__ __forceinline__ float softplusf(float x){ return x > 20.0f ? x : log1pf(expf(x)); }

__device__ __forceinline__ void st_rel(unsigned* p, unsigned v){
    asm volatile("st.global.release.gpu.u32 [%0], %1;" :: "l"(p), "r"(v) : "memory");
}
__device__ __forceinline__ unsigned ld_acq(unsigned* p){
    unsigned v;
    asm volatile("ld.global.acquire.gpu.u32 %0, [%1];" : "=r"(v) : "l"(p) : "memory");
    return v;
}

// monotonic-epoch grid barrier
__device__ __forceinline__ void gbar(unsigned k)
{
    __syncthreads();
    if (threadIdx.x == 0){
        __threadfence();
        unsigned prev = atomicAdd(&g_barcnt, 1u);
        if (prev == k*NBLK - 1u){
            st_rel(&g_relgen, k);
        } else {
            while ((int)(ld_acq(&g_relgen) - k) < 0) {}
        }
    }
    __syncthreads();
}

__global__ void __launch_bounds__(NTHR) mamba_fused(
    const float* __restrict__ mha, const unsigned char* __restrict__ mask,
    const float* __restrict__ w1,  const float* __restrict__ b1,
    const float* __restrict__ w2,  const float* __restrict__ b2,
    const float* __restrict__ inw, const float* __restrict__ cw,
    const float* __restrict__ cb,  const float* __restrict__ xpw,
    const float* __restrict__ dtw, const float* __restrict__ dtb,
    const float* __restrict__ alg, const float* __restrict__ dsk,
    const float* __restrict__ ow,  const float* __restrict__ bnw,
    const float* __restrict__ nfw, float* __restrict__ out)
{
    const int blk = blockIdx.x, tid = threadIdx.x;
    __shared__ __align__(16) float smem[5504];   // 22 KB staging
    __shared__ float sRed[16];
    __shared__ unsigned sVal[8];
    unsigned k = ld_acq(&g_relgen);              // stable epoch base

    const int b  = blk >> 4;
    const int tg = blk & 15;
    const int t0 = tg * 4;
    const int j  = tid & 127;       // output channel for DM-wide GEMMs
    const int th = tid >> 7;        // token-half: tokens {th*2, th*2+1}
    const int wg = (tid >> 5) & 3;  // warp within token-half

    // =============== P0: MLP (gelu) + residual init + rmsnorm(layer 0) ===============
    {
        float* xs = smem;            // [4][128]
        float* h1 = smem + 512;      // [4][128]
        const float* xb = mha + ((size_t)(b*4096 + t0)) * DM;  // (b, n=0, t0.., :)
        for (int i = tid; i < 512; i += NTHR) xs[i] = xb[i];
        __syncthreads();

        float a[2];
        {   float bb = b1[j]; a[0]=a[1]=bb;
            const float4* wr = (const float4*)(w1 + (size_t)j*DM);
            #pragma unroll 8
            for (int q = 0; q < DM/4; q++){
                float4 w = wr[q];
                #pragma unroll
                for (int s = 0; s < 2; s++){
                    float4 v = ((const float4*)(xs + (th*2 + s)*DM))[q];
                    a[s] += w.x*v.x + w.y*v.y + w.z*v.z + w.w*v.w;
                }
            }
        }
        __syncthreads();
        #pragma unroll
        for (int s = 0; s < 2; s++) h1[(th*2 + s)*DM + j] = geluf(a[s]);
        __syncthreads();
        {   float bb = b2[j]; a[0]=a[1]=bb;
            const float4* wr = (const float4*)(w2 + (size_t)j*DM);
            #pragma unroll 8
            for (int q = 0; q < DM/4; q++){
                float4 w = wr[q];
                #pragma unroll
                for (int s = 0; s < 2; s++){
                    float4 v = ((const float4*)(h1 + (th*2 + s)*DM))[q];
                    a[s] += w.x*v.x + w.y*v.y + w.z*v.z + w.w*v.w;
                }
            }
        }
        #pragma unroll
        for (int s = 0; s < 2; s++){
            const int tt = th*2 + s;
            g_res[(b*LEN + t0 + tt)*DM + j] = a[s];
            float r2 = a[s]*a[s];
            #pragma unroll
            for (int o = 16; o > 0; o >>= 1) r2 += __shfl_xor_sync(0xffffffffu, r2, o);
            if ((tid & 31) == 0) sRed[tt*4 + wg] = r2;
        }
        __syncthreads();
        #pragma unroll
        for (int s = 0; s < 2; s++){
            const int tt = th*2 + s;
            float r2 = sRed[tt*4+0] + sRed[tt*4+1] + sRed[tt*4+2] + sRed[tt*4+3];
            g_hn[(b*LEN + t0 + tt)*DM + j] = a[s] * rsqrtf(r2*(1.0f/DM) + EPSF) * bnw[j];
        }
    }
    gbar(++k);

    // =============== layers ===============
    for (int L = 0; L < 4; L++){
        // ---- AB: in_proj (3-token halo) + conv + x_proj + dt_proj ----
        {
            float* xs  = smem;           // [7][128] hn tokens t0-3..t0+3
            float* xcs = smem + 896;     // [7][256] xc
            float* su  = smem + 2688;    // [4][256] u (own tokens)
            float* sDt = smem + 3712;    // [4][8]
            for (int i = tid; i < 896; i += NTHR){
                const int s = i >> 7, t = t0 - 3 + s;
                xs[i] = (t >= 0) ? __ldcg(g_hn + (b*LEN + t)*DM + (i & 127)) : 0.0f;
            }
            __syncthreads();
            const float* Wi = inw + (size_t)L*2*DI*DM;
            // xc rows: r = tid (0..255), 7 tokens
            {
                const float4* wr = (const float4*)(Wi + (size_t)tid*DM);
                float a[7] = {0,0,0,0,0,0,0};
                #pragma unroll 4
                for (int q = 0; q < DM/4; q++){
                    float4 w = wr[q];
                    #pragma unroll
                    for (int s = 0; s < 7; s++){
                        float4 v = ((const float4*)(xs + s*128))[q];
                        a[s] += w.x*v.x + w.y*v.y + w.z*v.z + w.w*v.w;
                    }
                }
                #pragma unroll
                for (int s = 0; s < 7; s++) xcs[s*256 + tid] = a[s];
            }
            // z rows: c = tid, own 4 tokens
            {
                const float4* wr = (const float4*)(Wi + (size_t)(DI + tid)*DM);
                float a[4] = {0,0,0,0};
                #pragma unroll 8
                for (int q = 0; q < DM/4; q++){
                    float4 w = wr[q];
                    #pragma unroll
                    for (int s = 0; s < 4; s++){
                        float4 v = ((const float4*)(xs + (3 + s)*128))[q];
                        a[s] += w.x*v.x + w.y*v.y + w.z*v.z + w.w*v.w;
                    }
                }
                *(float4*)(g_zs + (b*DI + tid)*LEN + t0) =
                    make_float4(siluf(a[0]), siluf(a[1]), siluf(a[2]), siluf(a[3]));
            }
            __syncthreads();
            // conv (width 4) + silu: c = tid
            {
                const int c = tid;
                float4 wv = *(const float4*)(cw + ((size_t)L*DI + c)*4);
                const float bb = cb[L*DI + c];
                float xv[7];
                #pragma unroll
                for (int s = 0; s < 7; s++) xv[s] = xcs[s*256 + c];
                float u4[4];
                #pragma unroll
                for (int jj = 0; jj < 4; jj++){
                    float y = bb + wv.x*xv[jj] + wv.y*xv[jj+1] + wv.z*xv[jj+2] + wv.w*xv[jj+3];
                    u4[jj] = siluf(y);
                    su[jj*256 + c] = u4[jj];
                }
                *(float4*)(g_ucm + (b*DI + c)*LEN + t0) =
                    make_float4(u4[0], u4[1], u4[2], u4[3]);
            }
            __syncthreads();
            // x_proj: 40 outs x 4 tokens = 160 tasks
            if (tid < 160){
                const int kk = tid % 40, tt = tid / 40;
                const float* xw = xpw + (size_t)L*(DTR + 2*DS)*DI;
                const float4* wr = (const float4*)(xw + (size_t)kk*DI);
                const float4* uv = (const float4*)(su + tt*256);
                float a = 0.0f;
                #pragma unroll 8
                for (int q = 0; q < DI/4; q++){
                    float4 w = wr[q], v = uv[q];
                    a += w.x*v.x + w.y*v.y + w.z*v.z + w.w*v.w;
                }
                const int t = t0 + tt;
                if (kk < DTR)            sDt[tt*DTR + kk] = a;
                else if (kk < DTR + DS)  g_Bm[(b*LEN + t)*DS + (kk - DTR)]      = a;
                else                     g_Cm[(b*LEN + t)*DS + (kk - DTR - DS)] = a;
            }
            __syncthreads();
            // dt_proj + softplus: c = tid
            {
                const int c = tid;
                const float* dw = dtw + (size_t)L*DI*DTR;
                float bb = dtb[L*DI + c];
                float wreg[DTR];
                #pragma unroll
                for (int r = 0; r < DTR; r++) wreg[r] = dw[c*DTR + r];
                float d4[4];
                #pragma unroll
                for (int tt = 0; tt < 4; tt++){
                    float a = bb;
                    #pragma unroll
                    for (int r = 0; r < DTR; r++) a += sDt[tt*DTR + r] * wreg[r];
                    d4[tt] = softplusf(a);
                }
                *(float4*)(g_dt + (b*DI + c)*LEN + t0) =
                    make_float4(d4[0], d4[1], d4[2], d4[3]);
            }
            __syncthreads();
        }
        gbar(++k);

        // ---- scan: 64 blocks; block=(b, 16-ch slice); thread=(cs, n) single state ----
        {
            const int sb = blk >> 4, c0 = (blk & 15)*16;
            float* sdt = smem;           // [16][72]
            float* suu = smem + 1152;    // [16][72]
            float* szz = smem + 2304;    // [16][72]
            float* sB  = smem + 3456;    // [64][16]
            float* sC  = smem + 4480;    // [64][16]
            {
                const int q = tid;       // 256 float4s each
                ((float4*)sB)[q] = __ldcg((const float4*)(g_Bm + sb*LEN*DS) + q);
                ((float4*)sC)[q] = __ldcg((const float4*)(g_Cm + sb*LEN*DS) + q);
                const int cs = q >> 4, qq = q & 15;
                *(float4*)(sdt + cs*72 + qq*4) =
                    __ldcg((const float4*)(g_dt  + (sb*DI + c0 + cs)*LEN) + qq);
                *(float4*)(suu + cs*72 + qq*4) =
                    __ldcg((const float4*)(g_ucm + (sb*DI + c0 + cs)*LEN) + qq);
                *(float4*)(szz + cs*72 + qq*4) =
                    __ldcg((const float4*)(g_zs  + (sb*DI + c0 + cs)*LEN) + qq);
            }
            __syncthreads();
            const int cs = tid >> 4, n = tid & 15, c = c0 + cs;
            const float A  = -expf(alg[((size_t)L*DI + c)*DS + n]);
            const float Dv = dsk[L*DI + c];
            const float* pd = sdt + cs*72;
            const float* pu = suu + cs*72;
            const float* pz = szz + cs*72;
            float h = 0.0f;
            for (int tq = 0; tq < 16; tq++){
                const int tb = tq*4;
                float4 dt4 = *(const float4*)(pd + tb);
                float4 u4  = *(const float4*)(pu + tb);
                const float* dta = (const float*)&dt4;
                const float* ua  = (const float*)&u4;
                float dA[4], y[4];
                #pragma unroll
                for (int s = 0; s < 4; s++) dA[s] = __expf(dta[s] * A);
                #pragma unroll
                for (int s = 0; s < 4; s++){
                    const float dtu = dta[s] * ua[s];
                    h = h*dA[s] + dtu * sB[(tb + s)*DS + n];
                    y[s] = h * sC[(tb + s)*DS + n];
                }
                #pragma unroll
                for (int o = 1; o < 16; o <<= 1){
                    #pragma unroll
                    for (int s = 0; s < 4; s++)
                        y[s] += __shfl_xor_sync(0xffffffffu, y[s], o, 16);
                }
                if (n == 0){
                    float4 z4 = *(const float4*)(pz + tb);
                    const float* za = (const float*)&z4;
                    #pragma unroll
                    for (int s = 0; s < 4; s++)
                        g_ys[(sb*LEN + tb + s)*DI + c] = (y[s] + ua[s]*Dv) * za[s];
                }
            }
            __syncthreads();
        }
        gbar(++k);

        // ---- D: out_proj + residual + rmsnorm(next) [+ fused final on L3] ----
        {
            float* sy = smem;        // [4][256]
            {
                const float* src = g_ys + (size_t)(b*LEN + t0)*DI;
                for (int i = tid; i < 1024; i += NTHR) sy[i] = __ldcg(src + i);
            }
            __syncthreads();
            const float* Wo = ow + (size_t)L*DM*DI;
            const float4* wr = (const float4*)(Wo + (size_t)j*DI);
            float a[2] = {0,0};
            #pragma unroll 8
            for (int q = 0; q < DI/4; q++){
                float4 w = wr[q];
                #pragma unroll
                for (int s = 0; s < 2; s++){
                    float4 v = ((const float4*)(sy + (th*2 + s)*DI))[q];
                    a[s] += w.x*v.x + w.y*v.y + w.z*v.z + w.w*v.w;
                }
            }
            float r[2];
            #pragma unroll
            for (int s = 0; s < 2; s++){
                const int tt = th*2 + s;
                const int idx = (b*LEN + t0 + tt)*DM + j;
                r[s] = a[s] + g_res[idx];
                g_res[idx] = r[s];
                float r2 = r[s]*r[s];
                #pragma unroll
                for (int o = 16; o > 0; o >>= 1) r2 += __shfl_xor_sync(0xffffffffu, r2, o);
                if ((tid & 31) == 0) sRed[tt*4 + wg] = r2;
            }
            __syncthreads();
            if (L < 3){
                const float* bw = bnw + (L + 1)*DM;
                #pragma unroll
                for (int s = 0; s < 2; s++){
                    const int tt = th*2 + s;
                    float r2 = sRed[tt*4+0] + sRed[tt*4+1] + sRed[tt*4+2] + sRed[tt*4+3];
                    g_hn[(b*LEN + t0 + tt)*DM + j] =
                        r[s] * rsqrtf(r2*(1.0f/DM) + EPSF) * bw[j];
                }
                __syncthreads();
            } else if (tg == 15){
                // fused final: token 63 = tt=3 (th=1, s=1)
                unsigned v = 0;
                if (tid < 64) v = (mask[b*4096 + tid] != 0) ? 1u : 0u;  // row (b, n=0, :)
                unsigned bal = __ballot_sync(0xffffffffu, v != 0u);
                if ((tid & 31) == 0) sVal[tid >> 5] = bal;
                __syncthreads();
                const int valid = ((sVal[0] | sVal[1]) != 0u) ? 1 : 0;
                if (th == 1){
                    float r2 = sRed[12] + sRed[13] + sRed[14] + sRed[15];
                    float o = r[1] * rsqrtf(r2*(1.0f/DM) + EPSF) * nfw[j];
                    out[b*DM + j] = valid ? o : 0.0f;
                }
            }
        }
        if (L < 3) gbar(++k);
    }
}

// --------------------------------- launch ---------------------------------
extern "C" void kernel_launch(void* const* d_in, const int* in_sizes, int n_in,
                              void* d_out, int out_size)
{
    const float* mha = (const float*)d_in[0];
    const unsigned char* mask = (const unsigned char*)d_in[1];
    const float* w1  = (const float*)d_in[2];
    const float* b1  = (const float*)d_in[3];
    const float* w2  = (const float*)d_in[4];
    const float* b2  = (const float*)d_in[5];
    const float* inw = (const float*)d_in[6];
    const float* cw  = (const float*)d_in[7];
    const float* cb  = (const float*)d_in[8];
    const float* xpw = (const float*)d_in[9];
    const float* dtw = (const float*)d_in[10];
    const float* dtb = (const float*)d_in[11];
    const float* alg = (const float*)d_in[12];
    const float* dsk = (const float*)d_in[13];
    const float* ow  = (const float*)d_in[14];
    const float* bnw = (const float*)d_in[15];
    const float* nfw = (const float*)d_in[16];
    float* out = (float*)d_out;

    mamba_fused<<<NBLK, NTHR>>>(mha, mask, w1, b1, w2, b2, inw, cw, cb,
                                xpw, dtw, dtb, alg, dsk, ow, bnw, nfw, out);
}